// round 7
// baseline (speedup 1.0000x reference)
#include <cuda_runtime.h>
#include <cuda_bf16.h>
#include <cstdint>

#define N_NODES 100000
#define N_EDGES 1600000
#define D 128
#define SCAN_BLOCKS 391   // 391*256 = 100096 >= N_NODES

// ---------------- scratch (device globals; no allocation) ----------------
__device__ int   g_deg[N_NODES];
__device__ int   g_cursor[N_NODES];
__device__ int   g_base[N_NODES + 1];
__device__ float g_dis[N_NODES];
__device__ int   g_src[N_EDGES];
__device__ int   g_bsum[SCAN_BLOCKS];
__device__ float g_h[(size_t)N_NODES * D];

// ---------------- packed f32x2 helpers ----------------
__device__ __forceinline__ unsigned long long pk2(float lo, float hi) {
    unsigned long long r;
    asm("mov.b64 %0, {%1, %2};" : "=l"(r) : "f"(lo), "f"(hi));
    return r;
}
__device__ __forceinline__ void unpk2(unsigned long long v, float& lo, float& hi) {
    asm("mov.b64 {%0, %1}, %2;" : "=f"(lo), "=f"(hi) : "l"(v));
}
__device__ __forceinline__ void fma2(unsigned long long& d, unsigned long long a,
                                     unsigned long long b) {
    asm("fma.rn.f32x2 %0, %1, %2, %0;" : "+l"(d) : "l"(a), "l"(b));
}

// ---------------- 1. init ----------------
__global__ void init_kernel() {
    int i = blockIdx.x * blockDim.x + threadIdx.x;
    if (i < N_NODES) g_deg[i] = 1;   // self loop
}

// ---------------- 2. degree histogram ----------------
__global__ void hist_kernel(const int* __restrict__ ei) {
    int e = blockIdx.x * blockDim.x + threadIdx.x;
    if (e < N_EDGES) {
        int col = ei[N_EDGES + e];
        if ((unsigned)col < (unsigned)N_NODES)
            atomicAdd(&g_deg[col], 1);
    }
}

// ---------------- 3a. per-block sums of (deg-1) ----------------
__global__ void scanA_kernel() {
    __shared__ int s[256];
    int t = threadIdx.x, i = blockIdx.x * 256 + t;
    int v = (i < N_NODES) ? g_deg[i] - 1 : 0;
    s[t] = v; __syncthreads();
    for (int o = 128; o > 0; o >>= 1) {
        if (t < o) s[t] += s[t + o];
        __syncthreads();
    }
    if (t == 0) g_bsum[blockIdx.x] = s[0];
}

// ---------------- 3b. scan block sums (exclusive) ----------------
__global__ void scanB_kernel() {
    __shared__ int s[512];
    int t = threadIdx.x;
    int v = (t < SCAN_BLOCKS) ? g_bsum[t] : 0;
    s[t] = v; __syncthreads();
    for (int o = 1; o < 512; o <<= 1) {
        int u = (t >= o) ? s[t - o] : 0;
        __syncthreads();
        s[t] += u;
        __syncthreads();
    }
    if (t < SCAN_BLOCKS) g_bsum[t] = s[t] - v;  // exclusive prefix of block sums
}

// ---------------- 3c. finalize base[], dis[], cursor ----------------
__global__ void scanC_kernel() {
    __shared__ int s[256];
    int t = threadIdx.x, i = blockIdx.x * 256 + t;
    int d = (i < N_NODES) ? g_deg[i] : 1;
    int v = (i < N_NODES) ? d - 1 : 0;
    s[t] = v; __syncthreads();
    for (int o = 1; o < 256; o <<= 1) {
        int u = (t >= o) ? s[t - o] : 0;
        __syncthreads();
        s[t] += u;
        __syncthreads();
    }
    int excl = s[t] - v + g_bsum[blockIdx.x];
    if (i < N_NODES) {
        g_base[i] = excl;
        g_cursor[i] = 0;
        g_dis[i] = rsqrtf((float)d);
    }
    if (i == N_NODES - 1) g_base[N_NODES] = excl + v;
}

// ---------------- 4. GEMM: h = x @ W^T (software-pipelined) ----------------
// W^T in smem (64KB), 2 CTAs/SM. x rows via LDG.64 float2, double-buffered:
// a_nxt(kk+2) issued before the FMA block of kk -> LDG latency fully hidden.
__global__ void __launch_bounds__(256, 2)
gemm_kernel(const float* __restrict__ x, const float* __restrict__ w) {
    extern __shared__ float wt[];   // wt[k][j] = W[j][k], 128x128

    const int tid = threadIdx.x;
    const int row0 = blockIdx.x * 128;

    // load W transposed (coalesced float4 in, conflict-free scalar out)
    for (int c = tid; c < 128 * 32; c += 256) {
        int j = c & 127, k4 = c >> 7;
        float4 v = *(const float4*)&w[j * D + k4 * 4];
        wt[(k4 * 4 + 0) * D + j] = v.x;
        wt[(k4 * 4 + 1) * D + j] = v.y;
        wt[(k4 * 4 + 2) * D + j] = v.z;
        wt[(k4 * 4 + 3) * D + j] = v.w;
    }
    __syncthreads();

    const int ty = tid >> 4;        // 0..15 -> rows ty*8..+8
    const int tx = tid & 15;        // 0..15 -> cols tx*8..+8
    const int m0 = ty * 8, j0 = tx * 8;

    // clamp row indices for safe loads; stores are guarded exactly
    const float* xr[8];
#pragma unroll
    for (int i = 0; i < 8; i++) {
        int row = row0 + m0 + i;
        if (row > N_NODES - 1) row = N_NODES - 1;
        xr[i] = x + (size_t)row * D;
    }

    unsigned long long acc[8][4];
#pragma unroll
    for (int i = 0; i < 8; i++)
#pragma unroll
        for (int j = 0; j < 4; j++) acc[i][j] = 0ull;

    // prologue: a for kk=0
    float2 a_cur[8], a_nxt[8];
#pragma unroll
    for (int i = 0; i < 8; i++) a_cur[i] = *(const float2*)(xr[i]);

#pragma unroll 2
    for (int kk = 0; kk < 128; kk += 2) {
        const int kn = (kk + 2) & 127;   // wrap: harmless in-bounds reload on last iter
        // prefetch next a (long-scoreboard covered by 64 FFMA2 below)
#pragma unroll
        for (int i = 0; i < 8; i++) a_nxt[i] = *(const float2*)(xr[i] + kn);

        // both dk's b-vectors issued up-front (LDS latency covered)
        float4 c0 = *(const float4*)&wt[kk * D + j0];
        float4 c1 = *(const float4*)&wt[kk * D + j0 + 4];
        float4 d0 = *(const float4*)&wt[(kk + 1) * D + j0];
        float4 d1 = *(const float4*)&wt[(kk + 1) * D + j0 + 4];

        unsigned long long bp[4];
        bp[0] = pk2(c0.x, c0.y); bp[1] = pk2(c0.z, c0.w);
        bp[2] = pk2(c1.x, c1.y); bp[3] = pk2(c1.z, c1.w);
#pragma unroll
        for (int i = 0; i < 8; i++) {
            unsigned long long ap = pk2(a_cur[i].x, a_cur[i].x);
            fma2(acc[i][0], ap, bp[0]); fma2(acc[i][1], ap, bp[1]);
            fma2(acc[i][2], ap, bp[2]); fma2(acc[i][3], ap, bp[3]);
        }
        bp[0] = pk2(d0.x, d0.y); bp[1] = pk2(d0.z, d0.w);
        bp[2] = pk2(d1.x, d1.y); bp[3] = pk2(d1.z, d1.w);
#pragma unroll
        for (int i = 0; i < 8; i++) {
            unsigned long long ap = pk2(a_cur[i].y, a_cur[i].y);
            fma2(acc[i][0], ap, bp[0]); fma2(acc[i][1], ap, bp[1]);
            fma2(acc[i][2], ap, bp[2]); fma2(acc[i][3], ap, bp[3]);
        }
#pragma unroll
        for (int i = 0; i < 8; i++) a_cur[i] = a_nxt[i];
    }

#pragma unroll
    for (int i = 0; i < 8; i++) {
        int row = row0 + m0 + i;
        if (row < N_NODES) {
            float4 r0, r1;
            unpk2(acc[i][0], r0.x, r0.y); unpk2(acc[i][1], r0.z, r0.w);
            unpk2(acc[i][2], r1.x, r1.y); unpk2(acc[i][3], r1.z, r1.w);
            *(float4*)&g_h[(size_t)row * D + j0] = r0;
            *(float4*)&g_h[(size_t)row * D + j0 + 4] = r1;
        }
    }
}

// ---------------- 5. scatter edges into CSR ----------------
__global__ void scatter_kernel(const int* __restrict__ ei) {
    int e = blockIdx.x * blockDim.x + threadIdx.x;
    if (e < N_EDGES) {
        int row = ei[e];
        int col = ei[N_EDGES + e];
        if ((unsigned)row < (unsigned)N_NODES && (unsigned)col < (unsigned)N_NODES) {
            int pos = g_base[col] + atomicAdd(&g_cursor[col], 1);
            if ((unsigned)pos < (unsigned)N_EDGES)
                g_src[pos] = row;
        }
    }
}

// ---------------- 6. aggregation: one warp per node (R2 form) ----------------
__global__ void agg_kernel(const float* __restrict__ bias, float* __restrict__ out) {
    int warp = (blockIdx.x * blockDim.x + threadIdx.x) >> 5;
    int lane = threadIdx.x & 31;
    if (warp >= N_NODES) return;
    const int n = warp;

    const float dn = g_dis[n];
    float4 acc = *(const float4*)&g_h[(size_t)n * D + lane * 4];
    float sl = dn * dn;
    acc.x *= sl; acc.y *= sl; acc.z *= sl; acc.w *= sl;

    const int s = g_base[n];
    const int e = g_base[n + 1];
    for (int idx = s; idx < e; idx++) {
        int r = g_src[idx];
        float sc = g_dis[r] * dn;
        float4 hv = *(const float4*)&g_h[(size_t)r * D + lane * 4];
        acc.x = fmaf(hv.x, sc, acc.x);
        acc.y = fmaf(hv.y, sc, acc.y);
        acc.z = fmaf(hv.z, sc, acc.z);
        acc.w = fmaf(hv.w, sc, acc.w);
    }

    float4 bb = *(const float4*)&bias[lane * 4];
    acc.x = fmaxf(acc.x + bb.x, 0.f);
    acc.y = fmaxf(acc.y + bb.y, 0.f);
    acc.z = fmaxf(acc.z + bb.z, 0.f);
    acc.w = fmaxf(acc.w + bb.w, 0.f);
    *(float4*)&out[(size_t)n * D + lane * 4] = acc;
}

// ---------------- launch ----------------
extern "C" void kernel_launch(void* const* d_in, const int* in_sizes, int n_in,
                              void* d_out, int out_size) {
    const float* x    = (const float*)d_in[0];
    const int*   ei   = (const int*)d_in[1];     // int32 (JAX x64 disabled)
    const float* w    = (const float*)d_in[2];
    const float* bias = (const float*)d_in[3];
    float*       out  = (float*)d_out;

    const int gemm_smem = D * D * (int)sizeof(float);   // 64KB (W only)
    cudaFuncSetAttribute(gemm_kernel, cudaFuncAttributeMaxDynamicSharedMemorySize,
                         gemm_smem);

    init_kernel<<<(N_NODES + 255) / 256, 256>>>();                      // idx 0
    hist_kernel<<<(N_EDGES + 255) / 256, 256>>>(ei);                    // idx 1
    scanA_kernel<<<SCAN_BLOCKS, 256>>>();                               // idx 2
    gemm_kernel<<<(N_NODES + 127) / 128, 256, gemm_smem>>>(x, w);       // idx 3 (profiled)
    scanB_kernel<<<1, 512>>>();                                         // idx 4
    scanC_kernel<<<SCAN_BLOCKS, 256>>>();                               // idx 5
    scatter_kernel<<<(N_EDGES + 255) / 256, 256>>>(ei);                 // idx 6
    agg_kernel<<<(N_NODES * 32 + 255) / 256, 256>>>(bias, out);         // idx 7
}